// round 9
// baseline (speedup 1.0000x reference)
#include <cuda_runtime.h>

// LSTM T=512, B=4096, I=10, H=20.
// R9: thread = (unit j, ONE gate, 2 batch rows) -> 80 threads per 2 rows,
// 163840 threads total = ~35 warps/SM (2x R8). Weights 15 u64 + bias = ~34 regs;
// launch_bounds(160,7): grid 1024 CTAs = ONE wave at 7 CTA/SM.
// Gate combine via small smem gbuf + 2 barriers/step; single-buffered h/x
// (reads complete before bar1, writes land between bar1 and bar2).
// fma.rn.f32x2 packed math; tanh.approx activations.

#define T_STEPS 512
#define BATCH   4096
#define ISZ     10
#define HSZ     20
#define ROWS_CTA 4
#define NTHREADS 160

#define G_STRIDE 84                 // gbuf row stride (pad: row0 banks 0-19, row1 20-31)
#define HBUF_F  (ROWS_CTA * HSZ)    // 80
#define GBUF_F  (ROWS_CTA * G_STRIDE)
#define XS_ROW  12
#define XS_F    (ROWS_CTA * XS_ROW) // 48

typedef unsigned long long u64;

__device__ __forceinline__ u64 pack2(float x, float y) {
    u64 r; asm("mov.b64 %0, {%1,%2};" : "=l"(r) : "f"(x), "f"(y)); return r;
}
__device__ __forceinline__ void unpack2(u64 v, float& x, float& y) {
    asm("mov.b64 {%0,%1}, %2;" : "=f"(x), "=f"(y) : "l"(v));
}
__device__ __forceinline__ u64 ffma2(u64 a, u64 b, u64 c) {
    u64 r; asm("fma.rn.f32x2 %0, %1, %2, %3;" : "=l"(r) : "l"(a), "l"(b), "l"(c));
    return r;
}
__device__ __forceinline__ float tanh_fast(float x) {
    float y; asm("tanh.approx.f32 %0, %1;" : "=f"(y) : "f"(x)); return y;
}

__global__ void __launch_bounds__(NTHREADS, 7) lstm_r9_kernel(
    const float* __restrict__ x,      // [T, B, I]
    const float* __restrict__ h0,     // [B, H]
    const float* __restrict__ c0,     // [B, H]
    const float* __restrict__ Wih,    // [4H, I]
    const float* __restrict__ Whh,    // [4H, H]
    const float* __restrict__ bih,    // [4H]
    const float* __restrict__ bhh,    // [4H]
    float* __restrict__ out,
    long long out_size)
{
    const int tid  = threadIdx.x;
    const int q    = tid / 80;            // group 0: rows 0,1 | group 1: rows 2,3
    const int slot = tid - q * 80;
    const int gate = slot / HSZ;          // 0:i 1:f 2:g 3:o
    const int j    = slot - gate * HSZ;
    const int rA   = 2 * q;               // local rows
    const int rB   = 2 * q + 1;
    const int bbase = blockIdx.x * ROWS_CTA;

    __shared__ __align__(16) float hbuf[HBUF_F];   // h(t), single buffer
    __shared__ __align__(16) float gbuf[GBUF_F];   // activated gates
    __shared__ __align__(16) float xs[XS_F];       // x(t), single buffer

    // ---- weights for my single gate-row (gate, j) ----
    const int wrow = gate * HSZ + j;
    u64 wx[5], wh[10], bias2;
    {
        const float* wr = Wih + wrow * ISZ;
#pragma unroll
        for (int k = 0; k < 5; k++)
            wx[k] = *reinterpret_cast<const u64*>(wr + 2 * k);
        const float* wr2 = Whh + wrow * HSZ;
#pragma unroll
        for (int k = 0; k < 10; k++)
            wh[k] = *reinterpret_cast<const u64*>(wr2 + 2 * k);
        bias2 = pack2(bih[wrow] + bhh[wrow], 0.0f);
    }
    const float s_ = (gate == 2) ? 1.0f : 0.5f;  // act = fma(tanh(s*z), s, 1-s)
    const float o_ = 1.0f - s_;

    // ---- roles ----
    const bool updater = (tid < 80);          // item: row=tid/20, unit=tid%20
    const int  urow = tid / HSZ;              // 0..3 (valid when updater)
    const int  uj   = tid - urow * HSZ;
    const bool stager = (tid >= 80 && tid < 100);
    const int  sidx = tid - 80;               // 0..19
    const int  srow = sidx / 5;
    const int  schk = sidx - srow * 5;

    // ---- init ----
    float c_ = 0.0f, h_ = 0.0f;
    if (updater) {
        c_ = c0[(size_t)(bbase + urow) * HSZ + uj];
        hbuf[urow * HSZ + uj] = h0[(size_t)(bbase + urow) * HSZ + uj];
    }
    const float* xcta = x + (size_t)bbase * ISZ;
    const size_t x_step = (size_t)BATCH * ISZ;
    if (stager) {
        const u64 v = *reinterpret_cast<const u64*>(xcta + srow * ISZ + schk * 2);
        *reinterpret_cast<u64*>(xs + srow * XS_ROW + schk * 2) = v;
    }
    __syncthreads();

    float* op = out + (size_t)(bbase + urow) * HSZ + uj;   // updaters use this
    const size_t o_step = (size_t)BATCH * HSZ;

    for (int t = 0; t < T_STEPS; t++) {
        // prefetch x[t+1] (consumed as STS between bar1 and bar2)
        u64 xpre = 0ull;
        if (stager) {
            const float* xq = xcta + (size_t)((t + 1 < T_STEPS) ? t + 1 : t) * x_step;
            xpre = *reinterpret_cast<const u64*>(xq + srow * ISZ + schk * 2);
        }

        // ---- gate phase: 2 accumulators (rows rA, rB), 30 ffma2 ----
        u64 aA = bias2, aB = bias2;
        {
            const float* xrA = xs + rA * XS_ROW;
            const float* xrB = xs + rB * XS_ROW;
            const ulonglong2 a01 = *reinterpret_cast<const ulonglong2*>(xrA);
            const ulonglong2 a23 = *reinterpret_cast<const ulonglong2*>(xrA + 4);
            const u64        a4  = *reinterpret_cast<const u64*>(xrA + 8);
            const ulonglong2 b01 = *reinterpret_cast<const ulonglong2*>(xrB);
            const ulonglong2 b23 = *reinterpret_cast<const ulonglong2*>(xrB + 4);
            const u64        b4  = *reinterpret_cast<const u64*>(xrB + 8);
            aA = ffma2(wx[0], a01.x, aA);  aB = ffma2(wx[0], b01.x, aB);
            aA = ffma2(wx[1], a01.y, aA);  aB = ffma2(wx[1], b01.y, aB);
            aA = ffma2(wx[2], a23.x, aA);  aB = ffma2(wx[2], b23.x, aB);
            aA = ffma2(wx[3], a23.y, aA);  aB = ffma2(wx[3], b23.y, aB);
            aA = ffma2(wx[4], a4,    aA);  aB = ffma2(wx[4], b4,    aB);
        }
        {
            const float* hA_ = hbuf + rA * HSZ;
            const float* hB_ = hbuf + rB * HSZ;
#pragma unroll
            for (int k4 = 0; k4 < 5; k4++) {
                const ulonglong2 va = *reinterpret_cast<const ulonglong2*>(hA_ + 4 * k4);
                const ulonglong2 vb = *reinterpret_cast<const ulonglong2*>(hB_ + 4 * k4);
                aA = ffma2(wh[2 * k4],     va.x, aA);
                aB = ffma2(wh[2 * k4],     vb.x, aB);
                aA = ffma2(wh[2 * k4 + 1], va.y, aA);
                aB = ffma2(wh[2 * k4 + 1], vb.y, aB);
            }
        }

        // activations
        float lo, hi;
        unpack2(aA, lo, hi);
        const float vA = fmaf(tanh_fast(s_ * (lo + hi)), s_, o_);
        unpack2(aB, lo, hi);
        const float vB = fmaf(tanh_fast(s_ * (lo + hi)), s_, o_);

        gbuf[rA * G_STRIDE + gate * HSZ + j] = vA;
        gbuf[rB * G_STRIDE + gate * HSZ + j] = vB;

        __syncthreads();   // bar1: gates visible; h(t)/x(t) reads all done

        // ---- update phase (tids 0-79) + x staging (tids 80-99) ----
        if (updater) {
            const float* gb = gbuf + urow * G_STRIDE + uj;
            const float gi = gb[0];
            const float gf = gb[HSZ];
            const float gg = gb[2 * HSZ];
            const float go = gb[3 * HSZ];
            c_ = fmaf(gf, c_, gi * gg);
            h_ = go * tanh_fast(c_);
            hbuf[urow * HSZ + uj] = h_;    // h(t+1), single buffer
            op[0] = h_;
        } else if (stager) {
            *reinterpret_cast<u64*>(xs + srow * XS_ROW + schk * 2) = xpre;
        }

        __syncthreads();   // bar2: h(t+1), x(t+1) visible

        op += o_step;
    }

    // ---- final h, c appended after outputs ----
    const long long base = (long long)T_STEPS * BATCH * HSZ;
    if (updater && out_size >= base + 2LL * BATCH * HSZ) {
        out[base + (size_t)(bbase + urow) * HSZ + uj] = h_;
        out[base + (size_t)BATCH * HSZ + (size_t)(bbase + urow) * HSZ + uj] = c_;
    }
}

extern "C" void kernel_launch(void* const* d_in, const int* in_sizes, int n_in,
                              void* d_out, int out_size) {
    const float* x   = (const float*)d_in[0];
    const float* h0  = (const float*)d_in[1];
    const float* c0  = (const float*)d_in[2];
    const float* Wih = (const float*)d_in[3];
    const float* Whh = (const float*)d_in[4];
    const float* bih = (const float*)d_in[5];
    const float* bhh = (const float*)d_in[6];
    float* out = (float*)d_out;

    dim3 grid(BATCH / ROWS_CTA);   // 1024 CTAs -> one wave at 7 CTA/SM
    dim3 block(NTHREADS);          // 160 threads
    lstm_r9_kernel<<<grid, block>>>(x, h0, c0, Wih, Whh, bih, bhh,
                                    out, (long long)out_size);
}

// round 10
// speedup vs baseline: 1.4933x; 1.4933x over previous
#include <cuda_runtime.h>

// LSTM T=512, B=4096, I=10, H=20.
// R10 = R8 structure (best so far): thread = (unit j, gate-pair, 2 rows),
// even lane (i,g), odd lane (f,o), 3 shfls route gates, every lane updates
// one row's (c,h). CHANGE: x lives in per-thread REGISTERS (prefetch t+1),
// no smem x staging, no stager role -> barrier protects only the h exchange.
// Weights register-resident; fma.rn.f32x2; tanh.approx; one barrier/step.

#define T_STEPS 512
#define BATCH   4096
#define ISZ     10
#define HSZ     20
#define ROWS_CTA 8
#define NTHREADS 160

typedef unsigned long long u64;

__device__ __forceinline__ u64 pack2(float x, float y) {
    u64 r; asm("mov.b64 %0, {%1,%2};" : "=l"(r) : "f"(x), "f"(y)); return r;
}
__device__ __forceinline__ void unpack2(u64 v, float& x, float& y) {
    asm("mov.b64 {%0,%1}, %2;" : "=f"(x), "=f"(y) : "l"(v));
}
__device__ __forceinline__ u64 ffma2(u64 a, u64 b, u64 c) {
    u64 r; asm("fma.rn.f32x2 %0, %1, %2, %3;" : "=l"(r) : "l"(a), "l"(b), "l"(c));
    return r;
}
__device__ __forceinline__ float tanh_fast(float x) {
    float y; asm("tanh.approx.f32 %0, %1;" : "=f"(y) : "f"(x)); return y;
}

#define HBUF_F (2 * ROWS_CTA * HSZ)        // 320 floats, double-buffered h

__global__ void __launch_bounds__(NTHREADS, 4) lstm_r10_kernel(
    const float* __restrict__ x,      // [T, B, I]
    const float* __restrict__ h0,     // [B, H]
    const float* __restrict__ c0,     // [B, H]
    const float* __restrict__ Wih,    // [4H, I]
    const float* __restrict__ Whh,    // [4H, H]
    const float* __restrict__ bih,    // [4H]
    const float* __restrict__ bhh,    // [4H]
    float* __restrict__ out,
    long long out_size)
{
    const int tid  = threadIdx.x;
    const int half = tid & 1;             // 0: (i,g)  1: (f,o)
    const int p    = tid >> 1;            // 0..79
    const int rg   = p / HSZ;             // 0..3
    const int j    = p % HSZ;
    const int rA   = rg;
    const int rB   = rg + 4;
    const int bA   = blockIdx.x * ROWS_CTA + rA;
    const int bB   = blockIdx.x * ROWS_CTA + rB;

    __shared__ __align__(16) float hbuf[HBUF_F];

    const int g0 = half ? 1 : 0;          // f | i   (sigmoid)
    const int g1 = half ? 3 : 2;          // o | g   (sigmoid | tanh)
    const float s1 = half ? 0.5f : 1.0f;
    const float o1 = 1.0f - s1;

    // ---- register-resident weights (2 gate-rows) ----
    u64 wx[2][5], wh[2][10], bias2[2];
    {
        const int rows[2] = {g0 * HSZ + j, g1 * HSZ + j};
#pragma unroll
        for (int q = 0; q < 2; q++) {
            const float* wr = Wih + rows[q] * ISZ;
#pragma unroll
            for (int k = 0; k < 5; k++)
                wx[q][k] = *reinterpret_cast<const u64*>(wr + 2 * k);
            const float* wr2 = Whh + rows[q] * HSZ;
#pragma unroll
            for (int k = 0; k < 10; k++)
                wh[q][k] = *reinterpret_cast<const u64*>(wr2 + 2 * k);
            bias2[q] = pack2(bih[rows[q]] + bhh[rows[q]], 0.0f);
        }
    }

    // ---- owned row for the state update: odd -> A, even -> B ----
    const int myrow = half ? rA : rB;
    const int bmy   = half ? bA : bB;

    float c_ = c0[(size_t)bmy * HSZ + j];
    float h_ = 0.0f;
    hbuf[myrow * HSZ + j] = h0[(size_t)bmy * HSZ + j];

    // ---- x in registers: both rows, current step ----
    const float* xA = x + (size_t)bA * ISZ;
    const float* xB = x + (size_t)bB * ISZ;
    const size_t x_step = (size_t)BATCH * ISZ;

    u64 xcA[5], xcB[5];
#pragma unroll
    for (int k = 0; k < 5; k++) {
        xcA[k] = *reinterpret_cast<const u64*>(xA + 2 * k);
        xcB[k] = *reinterpret_cast<const u64*>(xB + 2 * k);
    }
    __syncthreads();

    float* opmy = out + (size_t)bmy * HSZ + j;
    const size_t o_step = (size_t)BATCH * HSZ;

    for (int t = 0; t < T_STEPS; t++) {
        const int cur = t & 1;

        // prefetch x[t+1] into regs (consumed next iteration; covers full step)
        u64 xnA[5], xnB[5];
        {
            const size_t off = (size_t)((t + 1 < T_STEPS) ? t + 1 : t) * x_step;
            const float* qA = xA + off;
            const float* qB = xB + off;
#pragma unroll
            for (int k = 0; k < 5; k++) {
                xnA[k] = *reinterpret_cast<const u64*>(qA + 2 * k);
                xnB[k] = *reinterpret_cast<const u64*>(qB + 2 * k);
            }
        }

        // ---- projections ----
        u64 aA0 = bias2[0], aA1 = bias2[1], aB0 = bias2[0], aB1 = bias2[1];
#pragma unroll
        for (int k = 0; k < 5; k++) {
            aA0 = ffma2(wx[0][k], xcA[k], aA0);
            aA1 = ffma2(wx[1][k], xcA[k], aA1);
            aB0 = ffma2(wx[0][k], xcB[k], aB0);
            aB1 = ffma2(wx[1][k], xcB[k], aB1);
        }
        {
            const float* hA_ = hbuf + cur * (ROWS_CTA * HSZ) + rA * HSZ;
            const float* hB_ = hbuf + cur * (ROWS_CTA * HSZ) + rB * HSZ;
#pragma unroll
            for (int k4 = 0; k4 < 5; k4++) {
                const ulonglong2 va = *reinterpret_cast<const ulonglong2*>(hA_ + 4 * k4);
                const ulonglong2 vb = *reinterpret_cast<const ulonglong2*>(hB_ + 4 * k4);
                aA0 = ffma2(wh[0][2 * k4],     va.x, aA0);
                aA1 = ffma2(wh[1][2 * k4],     va.x, aA1);
                aA0 = ffma2(wh[0][2 * k4 + 1], va.y, aA0);
                aA1 = ffma2(wh[1][2 * k4 + 1], va.y, aA1);
                aB0 = ffma2(wh[0][2 * k4],     vb.x, aB0);
                aB1 = ffma2(wh[1][2 * k4],     vb.x, aB1);
                aB0 = ffma2(wh[0][2 * k4 + 1], vb.y, aB0);
                aB1 = ffma2(wh[1][2 * k4 + 1], vb.y, aB1);
            }
        }

        // ---- activations ----
        float lo, hi;
        unpack2(aA0, lo, hi);
        const float vA0 = fmaf(tanh_fast(0.5f * (lo + hi)), 0.5f, 0.5f); // i|f (A)
        unpack2(aA1, lo, hi);
        const float vA1 = fmaf(tanh_fast(s1 * (lo + hi)), s1, o1);       // g|o (A)
        unpack2(aB0, lo, hi);
        const float vB0 = fmaf(tanh_fast(0.5f * (lo + hi)), 0.5f, 0.5f); // i|f (B)
        unpack2(aB1, lo, hi);
        const float vB1 = fmaf(tanh_fast(s1 * (lo + hi)), s1, o1);       // g|o (B)

        // even lane: tA = iA*gA, tB = iB*gB
        const float tA = vA0 * vA1;
        const float tB = vB0 * vB1;

        // route: odd gets iA*gA; even gets fB, oB
        const float rAp = __shfl_xor_sync(0xFFFFFFFFu, tA,  1);
        const float rB0 = __shfl_xor_sync(0xFFFFFFFFu, vB0, 1);
        const float rB1 = __shfl_xor_sync(0xFFFFFFFFu, vB1, 1);

        const float f_eff = half ? vA0 : rB0;
        const float p_eff = half ? rAp : tB;
        const float o_eff = half ? vA1 : rB1;
        c_ = fmaf(f_eff, c_, p_eff);
        const float th = tanh_fast(c_);
        h_ = o_eff * th;

        // h STS first (barrier dependency), then fire-and-forget STG
        hbuf[(cur ^ 1) * (ROWS_CTA * HSZ) + myrow * HSZ + j] = h_;
        opmy[0] = h_;

        // rotate x regs
#pragma unroll
        for (int k = 0; k < 5; k++) { xcA[k] = xnA[k]; xcB[k] = xnB[k]; }

        __syncthreads();
        opmy += o_step;
    }

    // ---- final h, c ----
    const long long base = (long long)T_STEPS * BATCH * HSZ;
    if (out_size >= base + 2LL * BATCH * HSZ) {
        out[base + (size_t)bmy * HSZ + j] = h_;
        out[base + (size_t)BATCH * HSZ + (size_t)bmy * HSZ + j] = c_;
    }
}

extern "C" void kernel_launch(void* const* d_in, const int* in_sizes, int n_in,
                              void* d_out, int out_size) {
    const float* x   = (const float*)d_in[0];
    const float* h0  = (const float*)d_in[1];
    const float* c0  = (const float*)d_in[2];
    const float* Wih = (const float*)d_in[3];
    const float* Whh = (const float*)d_in[4];
    const float* bih = (const float*)d_in[5];
    const float* bhh = (const float*)d_in[6];
    float* out = (float*)d_out;

    dim3 grid(BATCH / ROWS_CTA);   // 512 CTAs -> one resident wave at 4 CTA/SM
    dim3 block(NTHREADS);          // 160 threads
    lstm_r10_kernel<<<grid, block>>>(x, h0, c0, Wih, Whh, bih, bhh,
                                     out, (long long)out_size);
}

// round 11
// speedup vs baseline: 1.4989x; 1.0038x over previous
#include <cuda_runtime.h>

// LSTM T=512, B=4096, I=10, H=20.
// R10 = R8 structure (best so far): thread = (unit j, gate-pair, 2 rows),
// even lane (i,g), odd lane (f,o), 3 shfls route gates, every lane updates
// one row's (c,h). CHANGE: x lives in per-thread REGISTERS (prefetch t+1),
// no smem x staging, no stager role -> barrier protects only the h exchange.
// Weights register-resident; fma.rn.f32x2; tanh.approx; one barrier/step.

#define T_STEPS 512
#define BATCH   4096
#define ISZ     10
#define HSZ     20
#define ROWS_CTA 8
#define NTHREADS 160

typedef unsigned long long u64;

__device__ __forceinline__ u64 pack2(float x, float y) {
    u64 r; asm("mov.b64 %0, {%1,%2};" : "=l"(r) : "f"(x), "f"(y)); return r;
}
__device__ __forceinline__ void unpack2(u64 v, float& x, float& y) {
    asm("mov.b64 {%0,%1}, %2;" : "=f"(x), "=f"(y) : "l"(v));
}
__device__ __forceinline__ u64 ffma2(u64 a, u64 b, u64 c) {
    u64 r; asm("fma.rn.f32x2 %0, %1, %2, %3;" : "=l"(r) : "l"(a), "l"(b), "l"(c));
    return r;
}
__device__ __forceinline__ float tanh_fast(float x) {
    float y; asm("tanh.approx.f32 %0, %1;" : "=f"(y) : "f"(x)); return y;
}

#define HBUF_F (2 * ROWS_CTA * HSZ)        // 320 floats, double-buffered h

__global__ void __launch_bounds__(NTHREADS, 4) lstm_r10_kernel(
    const float* __restrict__ x,      // [T, B, I]
    const float* __restrict__ h0,     // [B, H]
    const float* __restrict__ c0,     // [B, H]
    const float* __restrict__ Wih,    // [4H, I]
    const float* __restrict__ Whh,    // [4H, H]
    const float* __restrict__ bih,    // [4H]
    const float* __restrict__ bhh,    // [4H]
    float* __restrict__ out,
    long long out_size)
{
    const int tid  = threadIdx.x;
    const int half = tid & 1;             // 0: (i,g)  1: (f,o)
    const int p    = tid >> 1;            // 0..79
    const int rg   = p / HSZ;             // 0..3
    const int j    = p % HSZ;
    const int rA   = rg;
    const int rB   = rg + 4;
    const int bA   = blockIdx.x * ROWS_CTA + rA;
    const int bB   = blockIdx.x * ROWS_CTA + rB;

    __shared__ __align__(16) float hbuf[HBUF_F];

    const int g0 = half ? 1 : 0;          // f | i   (sigmoid)
    const int g1 = half ? 3 : 2;          // o | g   (sigmoid | tanh)
    const float s1 = half ? 0.5f : 1.0f;
    const float o1 = 1.0f - s1;

    // ---- register-resident weights (2 gate-rows) ----
    u64 wx[2][5], wh[2][10], bias2[2];
    {
        const int rows[2] = {g0 * HSZ + j, g1 * HSZ + j};
#pragma unroll
        for (int q = 0; q < 2; q++) {
            const float* wr = Wih + rows[q] * ISZ;
#pragma unroll
            for (int k = 0; k < 5; k++)
                wx[q][k] = *reinterpret_cast<const u64*>(wr + 2 * k);
            const float* wr2 = Whh + rows[q] * HSZ;
#pragma unroll
            for (int k = 0; k < 10; k++)
                wh[q][k] = *reinterpret_cast<const u64*>(wr2 + 2 * k);
            bias2[q] = pack2(bih[rows[q]] + bhh[rows[q]], 0.0f);
        }
    }

    // ---- owned row for the state update: odd -> A, even -> B ----
    const int myrow = half ? rA : rB;
    const int bmy   = half ? bA : bB;

    float c_ = c0[(size_t)bmy * HSZ + j];
    float h_ = 0.0f;
    hbuf[myrow * HSZ + j] = h0[(size_t)bmy * HSZ + j];

    // ---- x in registers: both rows, current step ----
    const float* xA = x + (size_t)bA * ISZ;
    const float* xB = x + (size_t)bB * ISZ;
    const size_t x_step = (size_t)BATCH * ISZ;

    u64 xcA[5], xcB[5];
#pragma unroll
    for (int k = 0; k < 5; k++) {
        xcA[k] = *reinterpret_cast<const u64*>(xA + 2 * k);
        xcB[k] = *reinterpret_cast<const u64*>(xB + 2 * k);
    }
    __syncthreads();

    float* opmy = out + (size_t)bmy * HSZ + j;
    const size_t o_step = (size_t)BATCH * HSZ;

    for (int t = 0; t < T_STEPS; t++) {
        const int cur = t & 1;

        // prefetch x[t+1] into regs (consumed next iteration; covers full step)
        u64 xnA[5], xnB[5];
        {
            const size_t off = (size_t)((t + 1 < T_STEPS) ? t + 1 : t) * x_step;
            const float* qA = xA + off;
            const float* qB = xB + off;
#pragma unroll
            for (int k = 0; k < 5; k++) {
                xnA[k] = *reinterpret_cast<const u64*>(qA + 2 * k);
                xnB[k] = *reinterpret_cast<const u64*>(qB + 2 * k);
            }
        }

        // ---- projections ----
        u64 aA0 = bias2[0], aA1 = bias2[1], aB0 = bias2[0], aB1 = bias2[1];
#pragma unroll
        for (int k = 0; k < 5; k++) {
            aA0 = ffma2(wx[0][k], xcA[k], aA0);
            aA1 = ffma2(wx[1][k], xcA[k], aA1);
            aB0 = ffma2(wx[0][k], xcB[k], aB0);
            aB1 = ffma2(wx[1][k], xcB[k], aB1);
        }
        {
            const float* hA_ = hbuf + cur * (ROWS_CTA * HSZ) + rA * HSZ;
            const float* hB_ = hbuf + cur * (ROWS_CTA * HSZ) + rB * HSZ;
#pragma unroll
            for (int k4 = 0; k4 < 5; k4++) {
                const ulonglong2 va = *reinterpret_cast<const ulonglong2*>(hA_ + 4 * k4);
                const ulonglong2 vb = *reinterpret_cast<const ulonglong2*>(hB_ + 4 * k4);
                aA0 = ffma2(wh[0][2 * k4],     va.x, aA0);
                aA1 = ffma2(wh[1][2 * k4],     va.x, aA1);
                aA0 = ffma2(wh[0][2 * k4 + 1], va.y, aA0);
                aA1 = ffma2(wh[1][2 * k4 + 1], va.y, aA1);
                aB0 = ffma2(wh[0][2 * k4],     vb.x, aB0);
                aB1 = ffma2(wh[1][2 * k4],     vb.x, aB1);
                aB0 = ffma2(wh[0][2 * k4 + 1], vb.y, aB0);
                aB1 = ffma2(wh[1][2 * k4 + 1], vb.y, aB1);
            }
        }

        // ---- activations ----
        float lo, hi;
        unpack2(aA0, lo, hi);
        const float vA0 = fmaf(tanh_fast(0.5f * (lo + hi)), 0.5f, 0.5f); // i|f (A)
        unpack2(aA1, lo, hi);
        const float vA1 = fmaf(tanh_fast(s1 * (lo + hi)), s1, o1);       // g|o (A)
        unpack2(aB0, lo, hi);
        const float vB0 = fmaf(tanh_fast(0.5f * (lo + hi)), 0.5f, 0.5f); // i|f (B)
        unpack2(aB1, lo, hi);
        const float vB1 = fmaf(tanh_fast(s1 * (lo + hi)), s1, o1);       // g|o (B)

        // even lane: tA = iA*gA, tB = iB*gB
        const float tA = vA0 * vA1;
        const float tB = vB0 * vB1;

        // route: odd gets iA*gA; even gets fB, oB
        const float rAp = __shfl_xor_sync(0xFFFFFFFFu, tA,  1);
        const float rB0 = __shfl_xor_sync(0xFFFFFFFFu, vB0, 1);
        const float rB1 = __shfl_xor_sync(0xFFFFFFFFu, vB1, 1);

        const float f_eff = half ? vA0 : rB0;
        const float p_eff = half ? rAp : tB;
        const float o_eff = half ? vA1 : rB1;
        c_ = fmaf(f_eff, c_, p_eff);
        const float th = tanh_fast(c_);
        h_ = o_eff * th;

        // h STS first (barrier dependency), then fire-and-forget STG
        hbuf[(cur ^ 1) * (ROWS_CTA * HSZ) + myrow * HSZ + j] = h_;
        opmy[0] = h_;

        // rotate x regs
#pragma unroll
        for (int k = 0; k < 5; k++) { xcA[k] = xnA[k]; xcB[k] = xnB[k]; }

        __syncthreads();
        opmy += o_step;
    }

    // ---- final h, c ----
    const long long base = (long long)T_STEPS * BATCH * HSZ;
    if (out_size >= base + 2LL * BATCH * HSZ) {
        out[base + (size_t)bmy * HSZ + j] = h_;
        out[base + (size_t)BATCH * HSZ + (size_t)bmy * HSZ + j] = c_;
    }
}

extern "C" void kernel_launch(void* const* d_in, const int* in_sizes, int n_in,
                              void* d_out, int out_size) {
    const float* x   = (const float*)d_in[0];
    const float* h0  = (const float*)d_in[1];
    const float* c0  = (const float*)d_in[2];
    const float* Wih = (const float*)d_in[3];
    const float* Whh = (const float*)d_in[4];
    const float* bih = (const float*)d_in[5];
    const float* bhh = (const float*)d_in[6];
    float* out = (float*)d_out;

    dim3 grid(BATCH / ROWS_CTA);   // 512 CTAs -> one resident wave at 4 CTA/SM
    dim3 block(NTHREADS);          // 160 threads
    lstm_r10_kernel<<<grid, block>>>(x, h0, c0, Wih, Whh, bih, bhh,
                                     out, (long long)out_size);
}